// round 1
// baseline (speedup 1.0000x reference)
#include <cuda_runtime.h>
#include <math.h>

#define BATCH 1024
#define HID   512
#define VOC   512
#define TSTEPS 64
#define FH    2048   // 4*HID

// -------- persistent device scratch (no allocs allowed) --------
__device__ float g_EProj[VOC * FH];      // embedding @ W_ih^T + (b_ih+b_hh), 4MB
__device__ float g_h[2][BATCH * HID];    // double-buffered hidden state
__device__ float g_c[BATCH * HID];       // cell state (in-place safe: 1 writer/elem)
__device__ int   g_idx[BATCH];           // greedy token index feedback

// -------- packed fp32x2 helpers (sm_103a FFMA2 path) --------
__device__ __forceinline__ unsigned long long pack2(float x, float y) {
    unsigned long long r;
    asm("mov.b64 %0, {%1, %2};" : "=l"(r) : "f"(x), "f"(y));
    return r;
}
__device__ __forceinline__ float2 unpack2(unsigned long long v) {
    float2 r;
    asm("mov.b64 {%0, %1}, %2;" : "=f"(r.x), "=f"(r.y) : "l"(v));
    return r;
}
__device__ __forceinline__ void fma2(unsigned long long& d, unsigned long long a,
                                     unsigned long long b) {
    asm("fma.rn.f32x2 %0, %1, %2, %3;" : "=l"(d) : "l"(a), "l"(b), "l"(d));
}
// sigmoid via HW tanh: sigmoid(x) = 0.5*tanh(x/2)+0.5 (exact identity)
__device__ __forceinline__ float sigf(float x) { return 0.5f * tanhf(0.5f * x) + 0.5f; }

// ============================================================
// init: h0 = encoder_hidden, c0 = encoder_cell, idx = SOS(0)
// ============================================================
__global__ void __launch_bounds__(256) init_kernel(const float* __restrict__ eh,
                                                   const float* __restrict__ ec) {
    int i = blockIdx.x * blockDim.x + threadIdx.x;
    int stride = gridDim.x * blockDim.x;
    for (int k = i; k < BATCH * HID; k += stride) {
        g_h[0][k] = eh[k];
        g_c[k]    = ec[k];
    }
    if (i < BATCH) g_idx[i] = 0;
}

// ============================================================
// shared GEMM mainloop: C[64 rows][4 gates x 32 cols] over K=512
// A: 64 rows, K-contiguous.  B: rows (g*HID + j), K-contiguous (NT gemm).
// acc[g][m] holds f32x2 (2 adjacent j) for A-row (ty*4+m), gate g.
// ============================================================
struct __align__(16) Smem64 {
    float As[16][64];    // [k][b-row]
    float Bs[16][128];   // [k][g*32 + j]
};

__device__ __forceinline__ void gemm_mainloop(
    const float* __restrict__ aPtr,   // &A[blockRowBase + aRowL][aK]
    const float* __restrict__ bPtr,   // &B[globalBRow][bK]
    Smem64& s, unsigned long long acc[4][4],
    int ty, int tx, int aRowL, int aK, int nl, int bK)
{
    float4 aReg  = *(const float4*)(aPtr);
    float4 bReg0 = *(const float4*)(bPtr);
    float4 bReg1 = *(const float4*)(bPtr + 4);

    #pragma unroll 1
    for (int tt = 0; tt < HID / 16; tt++) {
        s.As[aK + 0][aRowL] = aReg.x;  s.As[aK + 1][aRowL] = aReg.y;
        s.As[aK + 2][aRowL] = aReg.z;  s.As[aK + 3][aRowL] = aReg.w;
        s.Bs[bK + 0][nl] = bReg0.x;  s.Bs[bK + 1][nl] = bReg0.y;
        s.Bs[bK + 2][nl] = bReg0.z;  s.Bs[bK + 3][nl] = bReg0.w;
        s.Bs[bK + 4][nl] = bReg1.x;  s.Bs[bK + 5][nl] = bReg1.y;
        s.Bs[bK + 6][nl] = bReg1.z;  s.Bs[bK + 7][nl] = bReg1.w;
        __syncthreads();

        if (tt + 1 < HID / 16) {   // prefetch next K-tile (latency hidden by compute)
            int k0 = (tt + 1) * 16;
            aReg  = *(const float4*)(aPtr + k0);
            bReg0 = *(const float4*)(bPtr + k0);
            bReg1 = *(const float4*)(bPtr + k0 + 4);
        }

        #pragma unroll
        for (int kk = 0; kk < 16; kk++) {
            float4 a = *(const float4*)&s.As[kk][ty * 4];
            unsigned long long a0 = pack2(a.x, a.x), a1 = pack2(a.y, a.y);
            unsigned long long a2 = pack2(a.z, a.z), a3 = pack2(a.w, a.w);
            #pragma unroll
            for (int g = 0; g < 4; g++) {
                unsigned long long bv =
                    *(const unsigned long long*)&s.Bs[kk][g * 32 + tx * 2];
                fma2(acc[g][0], a0, bv);
                fma2(acc[g][1], a1, bv);
                fma2(acc[g][2], a2, bv);
                fma2(acc[g][3], a3, bv);
            }
        }
        __syncthreads();
    }
}

// ============================================================
// E_proj precompute: E_proj[v][g*H+j] = emb[v]·W_ih[g*H+j] + b_ih + b_hh
// grid (16 j-tiles, 8 v-tiles), 256 threads
// ============================================================
__global__ void __launch_bounds__(256) eproj_kernel(
    const float* __restrict__ emb, const float* __restrict__ Wih,
    const float* __restrict__ b_ih, const float* __restrict__ b_hh)
{
    __shared__ Smem64 s;
    int tid = threadIdx.x, bx = blockIdx.x, by = blockIdx.y;
    int ty = tid >> 4, tx = tid & 15;
    int aRowL = tid >> 2, aK = (tid & 3) * 4;
    int nl = tid >> 1,   bK = (tid & 1) * 8;
    int bg = nl >> 5, bj = nl & 31;

    unsigned long long acc[4][4];
    #pragma unroll
    for (int g = 0; g < 4; g++)
        #pragma unroll
        for (int m = 0; m < 4; m++) acc[g][m] = 0ULL;

    const float* aPtr = emb + (size_t)(by * 64 + aRowL) * HID + aK;
    const float* bPtr = Wih + (size_t)(bg * HID + bx * 32 + bj) * HID + bK;
    gemm_mainloop(aPtr, bPtr, s, acc, ty, tx, aRowL, aK, nl, bK);

    int jBase = bx * 32 + tx * 2;
    #pragma unroll
    for (int m = 0; m < 4; m++) {
        int v = by * 64 + ty * 4 + m;
        #pragma unroll
        for (int g = 0; g < 4; g++) {
            float2 r = unpack2(acc[g][m]);
            int n0 = g * HID + jBase;
            r.x += b_ih[n0]     + b_hh[n0];
            r.y += b_ih[n0 + 1] + b_hh[n0 + 1];
            *(float2*)&g_EProj[(size_t)v * FH + n0] = r;
        }
    }
}

// ============================================================
// K1: gates = E_proj[idx[b]] + h @ W_hh^T, fused LSTM pointwise
// grid (16 j-tiles, 16 b-tiles), 256 threads
// ============================================================
__global__ void __launch_bounds__(256) lstm_step_kernel(const float* __restrict__ Whh,
                                                        int parity)
{
    __shared__ Smem64 s;
    const float* h_in  = g_h[parity];
    float*       h_out = g_h[parity ^ 1];

    int tid = threadIdx.x, bx = blockIdx.x, by = blockIdx.y;
    int ty = tid >> 4, tx = tid & 15;
    int aRowL = tid >> 2, aK = (tid & 3) * 4;
    int nl = tid >> 1,   bK = (tid & 1) * 8;
    int bg = nl >> 5, bj = nl & 31;

    unsigned long long acc[4][4];
    #pragma unroll
    for (int g = 0; g < 4; g++)
        #pragma unroll
        for (int m = 0; m < 4; m++) acc[g][m] = 0ULL;

    const float* aPtr = h_in + (size_t)(by * 64 + aRowL) * HID + aK;
    const float* bPtr = Whh  + (size_t)(bg * HID + bx * 32 + bj) * HID + bK;
    gemm_mainloop(aPtr, bPtr, s, acc, ty, tx, aRowL, aK, nl, bK);

    int jBase = bx * 32 + tx * 2;
    #pragma unroll
    for (int m = 0; m < 4; m++) {
        int b   = by * 64 + ty * 4 + m;
        int row = g_idx[b];
        const float* ep = g_EProj + (size_t)row * FH + jBase;

        float2 gi = unpack2(acc[0][m]);
        float2 gf = unpack2(acc[1][m]);
        float2 gg = unpack2(acc[2][m]);
        float2 go = unpack2(acc[3][m]);
        float2 e;
        e = *(const float2*)(ep +    0); gi.x += e.x; gi.y += e.y;
        e = *(const float2*)(ep +  512); gf.x += e.x; gf.y += e.y;
        e = *(const float2*)(ep + 1024); gg.x += e.x; gg.y += e.y;
        e = *(const float2*)(ep + 1536); go.x += e.x; go.y += e.y;

        float2 cold = *(const float2*)&g_c[(size_t)b * HID + jBase];
        float2 cn, hn;
        {
            float i_ = sigf(gi.x), f_ = sigf(gf.x), gv = tanhf(gg.x), o_ = sigf(go.x);
            cn.x = f_ * cold.x + i_ * gv;
            hn.x = o_ * tanhf(cn.x);
        }
        {
            float i_ = sigf(gi.y), f_ = sigf(gf.y), gv = tanhf(gg.y), o_ = sigf(go.y);
            cn.y = f_ * cold.y + i_ * gv;
            hn.y = o_ * tanhf(cn.y);
        }
        *(float2*)&g_c[(size_t)b * HID + jBase]   = cn;
        *(float2*)&h_out[(size_t)b * HID + jBase] = hn;
    }
}

// ============================================================
// K2: logits = h_new @ W_out^T + b_out; store out[t]; argmax -> g_idx
// grid 128 blocks (8 rows each), 256 threads; each thread: 1 row x 16 cols
// ============================================================
__global__ void __launch_bounds__(256) logits_kernel(
    const float* __restrict__ Wout, const float* __restrict__ bo,
    float* __restrict__ out_t, int parity)
{
    __shared__ __align__(16) float Bs[16][512];   // [k][n]
    __shared__ __align__(16) float As[16][8];     // [k][row]
    const float* h = g_h[parity];

    int tid = threadIdx.x, by = blockIdx.x;
    int ty = tid >> 5, tx = tid & 31;             // warp = one row
    int bRow = by * 8;

    unsigned long long acc[8];
    #pragma unroll
    for (int c = 0; c < 8; c++) acc[c] = 0ULL;

    float4 ar = make_float4(0.f, 0.f, 0.f, 0.f);
    float4 br[2][4];
    if (tid < 32)
        ar = *(const float4*)&h[(size_t)(bRow + (tid >> 2)) * HID + (tid & 3) * 4];
    #pragma unroll
    for (int r = 0; r < 2; r++)
        #pragma unroll
        for (int c = 0; c < 4; c++)
            br[r][c] = *(const float4*)&Wout[(size_t)(tid + r * 256) * HID + c * 4];

    #pragma unroll 1
    for (int tt = 0; tt < HID / 16; tt++) {
        if (tid < 32) {
            int rr = tid >> 2, kb = (tid & 3) * 4;
            As[kb + 0][rr] = ar.x;  As[kb + 1][rr] = ar.y;
            As[kb + 2][rr] = ar.z;  As[kb + 3][rr] = ar.w;
        }
        #pragma unroll
        for (int r = 0; r < 2; r++) {
            int n = tid + r * 256;
            #pragma unroll
            for (int c = 0; c < 4; c++) {
                Bs[c * 4 + 0][n] = br[r][c].x;  Bs[c * 4 + 1][n] = br[r][c].y;
                Bs[c * 4 + 2][n] = br[r][c].z;  Bs[c * 4 + 3][n] = br[r][c].w;
            }
        }
        __syncthreads();

        if (tt + 1 < HID / 16) {
            int k0 = (tt + 1) * 16;
            if (tid < 32)
                ar = *(const float4*)&h[(size_t)(bRow + (tid >> 2)) * HID + k0 + (tid & 3) * 4];
            #pragma unroll
            for (int r = 0; r < 2; r++)
                #pragma unroll
                for (int c = 0; c < 4; c++)
                    br[r][c] = *(const float4*)&Wout[(size_t)(tid + r * 256) * HID + k0 + c * 4];
        }

        #pragma unroll
        for (int kk = 0; kk < 16; kk++) {
            float a = As[kk][ty];
            unsigned long long a2 = pack2(a, a);
            #pragma unroll
            for (int c = 0; c < 4; c++) {
                union { float4 f; unsigned long long u[2]; } bb;
                bb.f = *(const float4*)&Bs[kk][tx * 4 + c * 128];
                fma2(acc[c * 2 + 0], a2, bb.u[0]);
                fma2(acc[c * 2 + 1], a2, bb.u[1]);
            }
        }
        __syncthreads();
    }

    // epilogue: +b_out, store logits, argmax (first-max tie-break like jnp.argmax)
    int b = bRow + ty;
    float best = -3.4e38f;
    int bestn = 0x7fffffff;
    float* orow = out_t + (size_t)b * VOC;
    #pragma unroll
    for (int c = 0; c < 4; c++) {
        int n0 = tx * 4 + c * 128;
        float4 bb = *(const float4*)&bo[n0];
        float2 l0 = unpack2(acc[c * 2 + 0]);
        float2 l1 = unpack2(acc[c * 2 + 1]);
        float v0 = l0.x + bb.x, v1 = l0.y + bb.y;
        float v2 = l1.x + bb.z, v3 = l1.y + bb.w;
        *(float4*)&orow[n0] = make_float4(v0, v1, v2, v3);
        if (v0 > best) { best = v0; bestn = n0; }
        if (v1 > best) { best = v1; bestn = n0 + 1; }
        if (v2 > best) { best = v2; bestn = n0 + 2; }
        if (v3 > best) { best = v3; bestn = n0 + 3; }
    }
    #pragma unroll
    for (int off = 16; off > 0; off >>= 1) {
        float om = __shfl_down_sync(0xffffffffu, best, off);
        int   on = __shfl_down_sync(0xffffffffu, bestn, off);
        if (om > best || (om == best && on < bestn)) { best = om; bestn = on; }
    }
    if (tx == 0) g_idx[b] = bestn;
}

// ============================================================
// launch: init, E_proj, then 64 x (lstm_step, logits) on default stream
// ============================================================
extern "C" void kernel_launch(void* const* d_in, const int* in_sizes, int n_in,
                              void* d_out, int out_size)
{
    // inputs in dict order: [target_var, target_max_len?, encoder_hidden,
    //  encoder_cell, embedding, W_ih, W_hh, b_ih, b_hh, W_out, b_out]
    // robust scan: first input of size B*H is encoder_hidden, rest follow in order
    int i = 0;
    while (i < n_in && in_sizes[i] != BATCH * HID) i++;
    const float* enc_h = (const float*)d_in[i];
    const float* enc_c = (const float*)d_in[i + 1];
    const float* emb   = (const float*)d_in[i + 2];
    const float* W_ih  = (const float*)d_in[i + 3];
    const float* W_hh  = (const float*)d_in[i + 4];
    const float* b_ih  = (const float*)d_in[i + 5];
    const float* b_hh  = (const float*)d_in[i + 6];
    const float* W_out = (const float*)d_in[i + 7];
    const float* b_out = (const float*)d_in[i + 8];
    float* out = (float*)d_out;

    init_kernel<<<512, 256>>>(enc_h, enc_c);
    eproj_kernel<<<dim3(16, 8), 256>>>(emb, W_ih, b_ih, b_hh);
    for (int t = 0; t < TSTEPS; t++) {
        lstm_step_kernel<<<dim3(16, 16), 256>>>(W_hh, t & 1);
        logits_kernel<<<128, 256>>>(W_out, b_out,
                                    out + (size_t)t * BATCH * VOC, (t & 1) ^ 1);
    }
}

// round 2
// speedup vs baseline: 1.6652x; 1.6652x over previous
#include <cuda_runtime.h>
#include <math.h>

#define BATCH 1024
#define HID   512
#define VOC   512
#define TSTEPS 64
#define FH    2048   // 4*HID

// -------- persistent device scratch (no allocs allowed) --------
__device__ float g_EProj[VOC * FH];            // embedding @ W_ih^T + bias, 4MB
__device__ float g_h[2][BATCH * HID];          // double-buffered hidden state
__device__ float g_c[BATCH * HID];             // cell state
__device__ unsigned long long g_key[2][BATCH]; // packed (value|~idx) argmax keys

// -------- packed fp32x2 helpers (sm_103a FFMA2 path) --------
__device__ __forceinline__ unsigned long long pack2(float x, float y) {
    unsigned long long r;
    asm("mov.b64 %0, {%1, %2};" : "=l"(r) : "f"(x), "f"(y));
    return r;
}
__device__ __forceinline__ float2 unpack2(unsigned long long v) {
    float2 r;
    asm("mov.b64 {%0, %1}, %2;" : "=f"(r.x), "=f"(r.y) : "l"(v));
    return r;
}
__device__ __forceinline__ void fma2(unsigned long long& d, unsigned long long a,
                                     unsigned long long b) {
    asm("fma.rn.f32x2 %0, %1, %2, %3;" : "=l"(d) : "l"(a), "l"(b), "l"(d));
}
// sigmoid via HW tanh path: sigmoid(x) = 0.5*tanh(x/2)+0.5 (exact identity)
__device__ __forceinline__ float sigf(float x) { return 0.5f * tanhf(0.5f * x) + 0.5f; }

// monotone float->uint (order-preserving), for argmax keys
__device__ __forceinline__ unsigned int fmono(float v) {
    unsigned int u = __float_as_uint(v);
    return u ^ ((unsigned int)((int)u >> 31) | 0x80000000u);
}

// ============================================================
// init: h0/c0 from encoder, key[0]=idx 0 (SOS), key[1]=0
// ============================================================
__global__ void __launch_bounds__(256) init_kernel(const float* __restrict__ eh,
                                                   const float* __restrict__ ec) {
    int i = blockIdx.x * blockDim.x + threadIdx.x;
    int stride = gridDim.x * blockDim.x;
    for (int k = i; k < BATCH * HID; k += stride) {
        g_h[0][k] = eh[k];
        g_c[k]    = ec[k];
    }
    if (i < BATCH) {
        g_key[0][i] = 0xFFFFFFFFull;  // low32 = ~0 -> idx = 0 (SOS)
        g_key[1][i] = 0ull;
    }
}

// ============================================================
// 128x128 GEMM mainloop (BK=16), 256 threads, 8x8 micro-tile.
// A: 128 rows (K-contig, stride HID). B rows: n = g*32+j -> global (g*HID + jBase + j).
// acc[g][m]: f32x2 over col pair (tx*2) of gate g, row (ty*8+m).
// ============================================================
struct __align__(16) SmemT {
    float As[16][128];   // [k][row]   conflict-free: STS lanes = consecutive rows
    float Bs[16][128];   // [k][g*32+j]
};

__device__ __forceinline__ void gemm_mainloop128(
    const float* __restrict__ aPtr,   // &A[rowBase + (tid&127)][ (tid>>7)*8 ]
    const float* __restrict__ bPtr,   // &B[globalBRow(tid&127)][ (tid>>7)*8 ]
    SmemT& s, unsigned long long acc[4][8], int ty, int tx, int rl, int kh)
{
    float4 aR0 = *(const float4*)(aPtr);
    float4 aR1 = *(const float4*)(aPtr + 4);
    float4 bR0 = *(const float4*)(bPtr);
    float4 bR1 = *(const float4*)(bPtr + 4);

    #pragma unroll 1
    for (int tt = 0; tt < HID / 16; tt++) {
        s.As[kh + 0][rl] = aR0.x;  s.As[kh + 1][rl] = aR0.y;
        s.As[kh + 2][rl] = aR0.z;  s.As[kh + 3][rl] = aR0.w;
        s.As[kh + 4][rl] = aR1.x;  s.As[kh + 5][rl] = aR1.y;
        s.As[kh + 6][rl] = aR1.z;  s.As[kh + 7][rl] = aR1.w;
        s.Bs[kh + 0][rl] = bR0.x;  s.Bs[kh + 1][rl] = bR0.y;
        s.Bs[kh + 2][rl] = bR0.z;  s.Bs[kh + 3][rl] = bR0.w;
        s.Bs[kh + 4][rl] = bR1.x;  s.Bs[kh + 5][rl] = bR1.y;
        s.Bs[kh + 6][rl] = bR1.z;  s.Bs[kh + 7][rl] = bR1.w;
        __syncthreads();

        if (tt + 1 < HID / 16) {   // prefetch next K-tile into regs
            int k0 = (tt + 1) * 16;
            aR0 = *(const float4*)(aPtr + k0);
            aR1 = *(const float4*)(aPtr + k0 + 4);
            bR0 = *(const float4*)(bPtr + k0);
            bR1 = *(const float4*)(bPtr + k0 + 4);
        }

        #pragma unroll
        for (int kk = 0; kk < 16; kk++) {
            float4 a0 = *(const float4*)&s.As[kk][ty * 8];
            float4 a1 = *(const float4*)&s.As[kk][ty * 8 + 4];
            unsigned long long A0 = pack2(a0.x, a0.x), A1 = pack2(a0.y, a0.y);
            unsigned long long A2 = pack2(a0.z, a0.z), A3 = pack2(a0.w, a0.w);
            unsigned long long A4 = pack2(a1.x, a1.x), A5 = pack2(a1.y, a1.y);
            unsigned long long A6 = pack2(a1.z, a1.z), A7 = pack2(a1.w, a1.w);
            #pragma unroll
            for (int g = 0; g < 4; g++) {
                unsigned long long bv =
                    *(const unsigned long long*)&s.Bs[kk][g * 32 + tx * 2];
                fma2(acc[g][0], A0, bv);  fma2(acc[g][1], A1, bv);
                fma2(acc[g][2], A2, bv);  fma2(acc[g][3], A3, bv);
                fma2(acc[g][4], A4, bv);  fma2(acc[g][5], A5, bv);
                fma2(acc[g][6], A6, bv);  fma2(acc[g][7], A7, bv);
            }
        }
        __syncthreads();
    }
}

// ============================================================
// E_proj precompute: E_proj[v][g*H+j] = emb[v]·W_ih[g*H+j] + b_ih + b_hh
// grid (16 j-tiles, 4 v-tiles of 128), 256 threads
// ============================================================
__global__ void __launch_bounds__(256) eproj_kernel(
    const float* __restrict__ emb, const float* __restrict__ Wih,
    const float* __restrict__ b_ih, const float* __restrict__ b_hh)
{
    __shared__ SmemT s;
    int tid = threadIdx.x, bx = blockIdx.x, by = blockIdx.y;
    int ty = tid >> 4, tx = tid & 15;
    int rl = tid & 127, kh = (tid >> 7) * 8;
    int bg = rl >> 5, bj = rl & 31;

    unsigned long long acc[4][8];
    #pragma unroll
    for (int g = 0; g < 4; g++)
        #pragma unroll
        for (int m = 0; m < 8; m++) acc[g][m] = 0ULL;

    const float* aPtr = emb + (size_t)(by * 128 + rl) * HID + kh;
    const float* bPtr = Wih + (size_t)(bg * HID + bx * 32 + bj) * HID + kh;
    gemm_mainloop128(aPtr, bPtr, s, acc, ty, tx, rl, kh);

    int jBase = bx * 32 + tx * 2;
    #pragma unroll
    for (int m = 0; m < 8; m++) {
        int v = by * 128 + ty * 8 + m;
        #pragma unroll
        for (int g = 0; g < 4; g++) {
            float2 r = unpack2(acc[g][m]);
            int n0 = g * HID + jBase;
            r.x += b_ih[n0]     + b_hh[n0];
            r.y += b_ih[n0 + 1] + b_hh[n0 + 1];
            *(float2*)&g_EProj[(size_t)v * FH + n0] = r;
        }
    }
}

// ============================================================
// K1: gates = E_proj[idx[b]] + h @ W_hh^T, fused LSTM pointwise
// grid (16 j-tiles, 8 b-tiles of 128), 256 threads
// ============================================================
__global__ void __launch_bounds__(256) lstm_step_kernel(const float* __restrict__ Whh,
                                                        int parity)
{
    __shared__ SmemT s;
    const float* h_in  = g_h[parity];
    float*       h_out = g_h[parity ^ 1];

    int tid = threadIdx.x, bx = blockIdx.x, by = blockIdx.y;
    int ty = tid >> 4, tx = tid & 15;
    int rl = tid & 127, kh = (tid >> 7) * 8;
    int bg = rl >> 5, bj = rl & 31;

    unsigned long long acc[4][8];
    #pragma unroll
    for (int g = 0; g < 4; g++)
        #pragma unroll
        for (int m = 0; m < 8; m++) acc[g][m] = 0ULL;

    const float* aPtr = h_in + (size_t)(by * 128 + rl) * HID + kh;
    const float* bPtr = Whh  + (size_t)(bg * HID + bx * 32 + bj) * HID + kh;
    gemm_mainloop128(aPtr, bPtr, s, acc, ty, tx, rl, kh);

    int jBase = bx * 32 + tx * 2;
    #pragma unroll
    for (int m = 0; m < 8; m++) {
        int b = by * 128 + ty * 8 + m;
        unsigned int row = 0xFFFFFFFFu - (unsigned int)(g_key[parity][b]);
        const float* ep = g_EProj + (size_t)row * FH + jBase;

        float2 gi = unpack2(acc[0][m]);
        float2 gf = unpack2(acc[1][m]);
        float2 gg = unpack2(acc[2][m]);
        float2 go = unpack2(acc[3][m]);
        float2 e;
        e = *(const float2*)(ep +    0); gi.x += e.x; gi.y += e.y;
        e = *(const float2*)(ep +  512); gf.x += e.x; gf.y += e.y;
        e = *(const float2*)(ep + 1024); gg.x += e.x; gg.y += e.y;
        e = *(const float2*)(ep + 1536); go.x += e.x; go.y += e.y;

        float2 cold = *(const float2*)&g_c[(size_t)b * HID + jBase];
        float2 cn, hn;
        {
            float i_ = sigf(gi.x), f_ = sigf(gf.x), gv = tanhf(gg.x), o_ = sigf(go.x);
            cn.x = f_ * cold.x + i_ * gv;
            hn.x = o_ * tanhf(cn.x);
        }
        {
            float i_ = sigf(gi.y), f_ = sigf(gf.y), gv = tanhf(gg.y), o_ = sigf(go.y);
            cn.y = f_ * cold.y + i_ * gv;
            hn.y = o_ * tanhf(cn.y);
        }
        *(float2*)&g_c[(size_t)b * HID + jBase]   = cn;
        *(float2*)&h_out[(size_t)b * HID + jBase] = hn;
    }
}

// ============================================================
// K2: logits = h_new @ W_out^T + b_out; store; fused argmax via atomicMax
// 64x64 tiles: grid (8 v-tiles, 16 b-tiles), 256 threads, 4x4 micro
// wb = key buffer written (for next step), zb = retired buffer to zero
// ============================================================
__global__ void __launch_bounds__(256) logits_kernel(
    const float* __restrict__ Wout, const float* __restrict__ bo,
    float* __restrict__ out_t, int parity, int wb, int zb)
{
    __shared__ __align__(16) float As[16][64];
    __shared__ __align__(16) float Bs[16][64];
    const float* h = g_h[parity];

    int tid = threadIdx.x, bx = blockIdx.x, by = blockIdx.y;

    // retire the old key buffer (safe: its readers finished last kernel,
    // its writers run next kernel; this kernel only atomics into g_key[wb])
    if (by == 0 && tid < 128) g_key[zb][bx * 128 + tid] = 0ull;

    int ty = tid >> 4, tx = tid & 15;
    int rl = tid & 63, kh = (tid >> 6) * 4;

    unsigned long long acc[4][2];
    #pragma unroll
    for (int m = 0; m < 4; m++) { acc[m][0] = 0ULL; acc[m][1] = 0ULL; }

    const float* aPtr = h    + (size_t)(by * 64 + rl) * HID + kh;
    const float* bPtr = Wout + (size_t)(bx * 64 + rl) * HID + kh;
    float4 aR = *(const float4*)(aPtr);
    float4 bR = *(const float4*)(bPtr);

    #pragma unroll 1
    for (int tt = 0; tt < HID / 16; tt++) {
        As[kh + 0][rl] = aR.x;  As[kh + 1][rl] = aR.y;
        As[kh + 2][rl] = aR.z;  As[kh + 3][rl] = aR.w;
        Bs[kh + 0][rl] = bR.x;  Bs[kh + 1][rl] = bR.y;
        Bs[kh + 2][rl] = bR.z;  Bs[kh + 3][rl] = bR.w;
        __syncthreads();

        if (tt + 1 < HID / 16) {
            int k0 = (tt + 1) * 16;
            aR = *(const float4*)(aPtr + k0);
            bR = *(const float4*)(bPtr + k0);
        }

        #pragma unroll
        for (int kk = 0; kk < 16; kk++) {
            float4 a = *(const float4*)&As[kk][ty * 4];
            union { float4 f; unsigned long long u[2]; } bb;
            bb.f = *(const float4*)&Bs[kk][tx * 4];
            unsigned long long A0 = pack2(a.x, a.x), A1 = pack2(a.y, a.y);
            unsigned long long A2 = pack2(a.z, a.z), A3 = pack2(a.w, a.w);
            fma2(acc[0][0], A0, bb.u[0]);  fma2(acc[0][1], A0, bb.u[1]);
            fma2(acc[1][0], A1, bb.u[0]);  fma2(acc[1][1], A1, bb.u[1]);
            fma2(acc[2][0], A2, bb.u[0]);  fma2(acc[2][1], A2, bb.u[1]);
            fma2(acc[3][0], A3, bb.u[0]);  fma2(acc[3][1], A3, bb.u[1]);
        }
        __syncthreads();
    }

    // epilogue: +b_out, store logits, per-row argmax key -> atomicMax
    int v0 = bx * 64 + tx * 4;
    float4 bb4 = *(const float4*)&bo[v0];
    #pragma unroll
    for (int m = 0; m < 4; m++) {
        int b = by * 64 + ty * 4 + m;
        float2 l0 = unpack2(acc[m][0]);
        float2 l1 = unpack2(acc[m][1]);
        float x0 = l0.x + bb4.x, x1 = l0.y + bb4.y;
        float x2 = l1.x + bb4.z, x3 = l1.y + bb4.w;
        *(float4*)&out_t[(size_t)b * VOC + v0] = make_float4(x0, x1, x2, x3);

        // key = (mono(value) << 32) | (0xFFFFFFFF - idx): max key == first-max
        unsigned long long key =
            ((unsigned long long)fmono(x0) << 32) | (0xFFFFFFFFu - (unsigned)(v0));
        unsigned long long k1 =
            ((unsigned long long)fmono(x1) << 32) | (0xFFFFFFFFu - (unsigned)(v0 + 1));
        unsigned long long k2 =
            ((unsigned long long)fmono(x2) << 32) | (0xFFFFFFFFu - (unsigned)(v0 + 2));
        unsigned long long k3 =
            ((unsigned long long)fmono(x3) << 32) | (0xFFFFFFFFu - (unsigned)(v0 + 3));
        if (k1 > key) key = k1;
        if (k2 > key) key = k2;
        if (k3 > key) key = k3;

        // reduce across the 16 lanes sharing this row (contiguous lane group)
        #pragma unroll
        for (int off = 8; off > 0; off >>= 1) {
            unsigned long long o = __shfl_down_sync(0xFFFFFFFFu, key, off);
            if (o > key) key = o;
        }
        if ((tid & 15) == 0)
            atomicMax(&g_key[wb][b], key);
    }
}

// ============================================================
// launch
// ============================================================
extern "C" void kernel_launch(void* const* d_in, const int* in_sizes, int n_in,
                              void* d_out, int out_size)
{
    // robust scan: first input of size B*H is encoder_hidden, rest follow in order
    int i = 0;
    while (i < n_in && in_sizes[i] != BATCH * HID) i++;
    const float* enc_h = (const float*)d_in[i];
    const float* enc_c = (const float*)d_in[i + 1];
    const float* emb   = (const float*)d_in[i + 2];
    const float* W_ih  = (const float*)d_in[i + 3];
    const float* W_hh  = (const float*)d_in[i + 4];
    const float* b_ih  = (const float*)d_in[i + 5];
    const float* b_hh  = (const float*)d_in[i + 6];
    const float* W_out = (const float*)d_in[i + 7];
    const float* b_out = (const float*)d_in[i + 8];
    float* out = (float*)d_out;

    init_kernel<<<512, 256>>>(enc_h, enc_c);
    eproj_kernel<<<dim3(16, 4), 256>>>(emb, W_ih, b_ih, b_hh);
    for (int t = 0; t < TSTEPS; t++) {
        lstm_step_kernel<<<dim3(16, 8), 256>>>(W_hh, t & 1);
        logits_kernel<<<dim3(8, 16), 256>>>(W_out, b_out,
                                            out + (size_t)t * BATCH * VOC,
                                            (t & 1) ^ 1,      // h parity to read
                                            (t + 1) & 1,      // key buffer to write
                                            t & 1);           // key buffer to retire
    }
}